// round 15
// baseline (speedup 1.0000x reference)
#include <cuda_runtime.h>
#include <math_constants.h>
#include <limits.h>

#define NPTS   8192
#define BATCH  4
#define KNN    4
#define QPB    224
#define THREADS 896                // 28 warps; 8 queries (4 pairs) per warp
#define GRPX   37                  // 37*4 = 148 blocks = 1 full wave
#define PAIRS  4

#define NBINS  512
#define XMIN   (-6.0f)
#define BINW   (12.0f / NBINS)
#define INVW   (NBINS / 12.0f)
#define SLACK  1e-3f
#define GUARD  64

#define PTS_BYTES ((NPTS + 2 * GUARD) * 16)
#define IDX_BYTES (NPTS * 4)
#define SMEM_BYTES (PTS_BYTES + 2 * IDX_BYTES + NBINS * 4 * 2)   // 203776 B

#define FULL 0xFFFFFFFFu

__device__ __forceinline__ int bin_of(float px) {
    int bin = (int)__fmul_rn(__fsub_rn(px, XMIN), INVW);
    return min(max(bin, 0), NBINS - 1);
}

__device__ __forceinline__ bool better(float s, int oj, float v, int iv) {
    return (s > v) | ((s == v) & (oj < iv));
}

__device__ __forceinline__ void insert4(float cs, int coj,
                                        float& v0, float& v1, float& v2, float& v3,
                                        int& o0, int& o1, int& o2, int& o3) {
    if (better(cs, coj, v3, o3)) {
        if (better(cs, coj, v2, o2)) {
            v3 = v2; o3 = o2;
            if (better(cs, coj, v1, o1)) {
                v2 = v1; o2 = o1;
                if (better(cs, coj, v0, o0)) {
                    v1 = v0; o1 = o0;
                    v0 = cs; o0 = coj;
                } else { v1 = cs; o1 = coj; }
            } else { v2 = cs; o2 = coj; }
        } else { v3 = cs; o3 = coj; }
    }
}

// Exact lexicographic top-4 of the 32-rank seed window via 4 butterfly rounds.
__device__ __forceinline__ void warp_seed(
    const float4* __restrict__ pts_s, const int* __restrict__ idx_s,
    int lo, int hi, int l, float qx, float qy, float qz,
    float& v0, float& v1, float& v2, float& v3,
    int& o0, int& o1, int& o2, int& o3)
{
    const int pos = lo + l;
    float s  = -CUDART_INF_F;
    int   oj = INT_MAX;
    if (pos <= hi) {
        const float4 p = pts_s[pos];
        s = __fmaf_rn(qx, p.x, p.w);
        s = __fmaf_rn(qy, p.y, s);
        s = __fmaf_rn(qz, p.z, s);
        oj = idx_s[pos];
    }
    float rs[KNN]; int ro[KNN];
    #pragma unroll
    for (int k = 0; k < KNN; ++k) {
        float bs = s; int boj = oj;
        #pragma unroll
        for (int d = 16; d; d >>= 1) {
            const float os  = __shfl_xor_sync(FULL, bs, d);
            const int   ooj = __shfl_xor_sync(FULL, boj, d);
            if (better(os, ooj, bs, boj)) { bs = os; boj = ooj; }
        }
        rs[k] = bs; ro[k] = boj;
        if (oj == boj) s = -CUDART_INF_F;     // oj unique -> mask winner
    }
    v0 = rs[0]; o0 = ro[0];
    v1 = rs[1]; o1 = ro[1];
    v2 = rs[2]; o2 = ro[2];
    v3 = rs[3]; o3 = ro[3];
}

__global__ __launch_bounds__(THREADS, 1)
void knn_sorted_kernel(const float* __restrict__ x, float* __restrict__ out) {
    extern __shared__ char smem_raw[];
    float4* __restrict__ pts_s   = (float4*)smem_raw + GUARD;
    int*    __restrict__ idx_s   = (int*)(smem_raw + PTS_BYTES);
    int*    __restrict__ rank_of = (int*)(smem_raw + PTS_BYTES + IDX_BYTES);
    int*    __restrict__ cnt     = (int*)(smem_raw + PTS_BYTES + 2 * IDX_BYTES);
    int*    __restrict__ tmp     = cnt + NBINS;

    const int b = blockIdx.y;
    const float* __restrict__ xb = x + (size_t)b * NPTS * 3;
    const int tid = threadIdx.x;

    // ---- 0) sentinels: beyond==true, s==-inf/NaN -> never a candidate
    if (tid < 2 * GUARD) {
        const int pos = (tid < GUARD) ? (tid - GUARD) : (NPTS + tid - GUARD);
        const float gx = (tid < GUARD) ? -1e30f : 1e30f;
        pts_s[pos] = make_float4(gx, 0.0f, 0.0f, -CUDART_INF_F);
    }

    // ---- 1) histogram over x-bins
    for (int i = tid; i < NBINS; i += THREADS) cnt[i] = 0;
    __syncthreads();
    for (int j = tid; j < NPTS; j += THREADS)
        atomicAdd(&cnt[bin_of(xb[3 * j])], 1);
    __syncthreads();

    // ---- 2) exclusive prefix (Kogge-Stone)
    if (tid < NBINS) tmp[tid] = cnt[tid];
    __syncthreads();
    for (int d = 1; d < NBINS; d <<= 1) {
        int v = 0;
        if (tid < NBINS && tid >= d) v = tmp[tid - d];
        __syncthreads();
        if (tid < NBINS) tmp[tid] += v;
        __syncthreads();
    }
    if (tid < NBINS) cnt[tid] = tmp[tid] - cnt[tid];
    __syncthreads();

    // ---- 3) scatter; record each original index's rank
    for (int j = tid; j < NPTS; j += THREADS) {
        float px = xb[3 * j + 0];
        float py = xb[3 * j + 1];
        float pz = xb[3 * j + 2];
        int pos = atomicAdd(&cnt[bin_of(px)], 1);
        pts_s[pos] = make_float4(px, py, pz, -0.5f * (px * px + py * py + pz * pz));
        idx_s[pos] = j;
        rank_of[j] = pos;
    }
    __syncthreads();

    // ---- 4) warp-cooperative paired queries
    const int w = tid >> 5, l = tid & 31;

    for (int pp = 0; pp < PAIRS; ++pp) {
        const int qA = blockIdx.x * QPB + w * (2 * PAIRS) + 2 * pp;
        const int qB = qA + 1;
        if (qA >= NPTS) break;
        const bool hasB = (qB < NPTS);

        // ---- query A state
        const int rA = rank_of[qA];
        const float4 qpA = pts_s[rA];
        const float qxA = qpA.x, qyA = qpA.y, qzA = qpA.z;
        const float qh2A = -2.0f * qpA.w;
        // ---- query B state (fall back to A if absent; its results are unused)
        const int rB = hasB ? rank_of[qB] : rA;
        const float4 qpB = pts_s[rB];
        const float qxB = qpB.x, qyB = qpB.y, qzB = qpB.z;
        const float qh2B = -2.0f * qpB.w;

        float va0, va1, va2, va3; int oa0, oa1, oa2, oa3;
        float vb0, vb1, vb2, vb3; int ob0, ob1, ob2, ob3;

        const int loA = max(0, rA - 16), hiA = min(NPTS - 1, rA + 15);
        const int loB = max(0, rB - 16), hiB = min(NPTS - 1, rB + 15);

        warp_seed(pts_s, idx_s, loA, hiA, l, qxA, qyA, qzA,
                  va0, va1, va2, va3, oa0, oa1, oa2, oa3);
        warp_seed(pts_s, idx_s, loB, hiB, l, qxB, qyB, qzB,
                  vb0, vb1, vb2, vb3, ob0, ob1, ob2, ob3);

        float xlimA = __fadd_ru(BINW, __fsqrt_ru(qh2A - 2.0f * va3 + SLACK));
        float xlimB = __fadd_ru(BINW, __fsqrt_ru(qh2B - 2.0f * vb3 + SLACK));

        // ---- walk both queries simultaneously, per direction
        #pragma unroll
        for (int dir = 0; dir < 2; ++dir) {
            const int step = dir ? -32 : 32;
            int posA = dir ? (loA - 1 - l) : (hiA + 1 + l);
            int posB = dir ? (loB - 1 - l) : (hiB + 1 + l);
            bool doneA = false, doneB = !hasB;

            while (!(doneA && doneB)) {
                const float4 pa = pts_s[posA];      // two independent LDS chains
                const float4 pb = pts_s[posB];
                const float dxA = dir ? (qxA - pa.x) : (pa.x - qxA);
                const float dxB = dir ? (qxB - pb.x) : (pb.x - qxB);
                float sA = __fmaf_rn(qxA, pa.x, pa.w);
                sA = __fmaf_rn(qyA, pa.y, sA);
                sA = __fmaf_rn(qzA, pa.z, sA);
                float sB = __fmaf_rn(qxB, pb.x, pb.w);
                sB = __fmaf_rn(qyB, pb.y, sB);
                sB = __fmaf_rn(qzB, pb.z, sB);
                const bool beyA = (dxA > xlimA) & !doneA;
                const bool beyB = (dxB > xlimB) & !doneB;
                const bool cA = (sA >= va3) & !doneA & (dxA <= xlimA);
                const bool cB = (sB >= vb3) & !doneB & (dxB <= xlimB);

                const unsigned evt = __ballot_sync(FULL, beyA | beyB | cA | cB);
                if (evt) {                           // rare after 32-wide seed
                    const unsigned bmA = __ballot_sync(FULL, beyA);
                    const unsigned bmB = __ballot_sync(FULL, beyB);
                    unsigned cmA = __ballot_sync(FULL, cA);
                    unsigned cmB = __ballot_sync(FULL, cB);
                    if (cmA) {
                        do {
                            const int src = __ffs(cmA) - 1;
                            cmA &= cmA - 1;
                            const float cs  = __shfl_sync(FULL, sA, src);
                            const int   cps = __shfl_sync(FULL, posA, src);
                            const int   coj = idx_s[cps];
                            insert4(cs, coj, va0, va1, va2, va3, oa0, oa1, oa2, oa3);
                        } while (cmA);
                        xlimA = __fadd_ru(BINW, __fsqrt_ru(qh2A - 2.0f * va3 + SLACK));
                    }
                    if (cmB) {
                        do {
                            const int src = __ffs(cmB) - 1;
                            cmB &= cmB - 1;
                            const float cs  = __shfl_sync(FULL, sB, src);
                            const int   cps = __shfl_sync(FULL, posB, src);
                            const int   coj = idx_s[cps];
                            insert4(cs, coj, vb0, vb1, vb2, vb3, ob0, ob1, ob2, ob3);
                        } while (cmB);
                        xlimB = __fadd_ru(BINW, __fsqrt_ru(qh2B - 2.0f * vb3 + SLACK));
                    }
                    doneA |= (bmA != 0);
                    doneB |= (bmB != 0);
                }
                if (!doneA) posA += step;
                if (!doneB) posB += step;
            }
        }

        // ---- 5) writes: lanes 0..3 emit one neighbor each (coords via rank_of)
        if (l < KNN) {
            const int oj = (l == 0) ? oa0 : (l == 1) ? oa1 : (l == 2) ? oa2 : oa3;
            const float4 nb = pts_s[rank_of[oj]];
            float* __restrict__ o = out + (((size_t)b * NPTS + qA) * KNN + l) * 3;
            o[0] = nb.x; o[1] = nb.y; o[2] = nb.z;
        }
        if (hasB && l >= 4 && l < 8) {
            const int e = l - 4;
            const int oj = (e == 0) ? ob0 : (e == 1) ? ob1 : (e == 2) ? ob2 : ob3;
            const float4 nb = pts_s[rank_of[oj]];
            float* __restrict__ o = out + (((size_t)b * NPTS + qB) * KNN + e) * 3;
            o[0] = nb.x; o[1] = nb.y; o[2] = nb.z;
        }
    }
}

extern "C" void kernel_launch(void* const* d_in, const int* in_sizes, int n_in,
                              void* d_out, int out_size) {
    (void)n_in; (void)in_sizes; (void)out_size;
    const float* x = (const float*)d_in[0];
    float* out = (float*)d_out;

    cudaFuncSetAttribute(knn_sorted_kernel,
                         cudaFuncAttributeMaxDynamicSharedMemorySize, SMEM_BYTES);

    dim3 grid(GRPX, BATCH, 1);   // 148 blocks = 1 full wave
    dim3 block(THREADS, 1, 1);
    knn_sorted_kernel<<<grid, block, SMEM_BYTES>>>(x, out);
}